// round 15
// baseline (speedup 1.0000x reference)
#include <cuda_runtime.h>
#include <cuda_bf16.h>
#include <cstdint>
#include <math.h>

#define Bn 4
#define Cn 64
#define Hn 96
#define Wn 96
#define HWn (Hn*Wn)
#define KKn 9

typedef unsigned long long ull;

// Scratch (device globals -- no dynamic allocation allowed)
__device__ __align__(16) float g_xt[Bn*HWn*Cn];   // x in NHWC: [b][h][w][c]
__device__ __align__(16) float g_offs[Bn*HWn*27]; // per pixel: 9 x (dy,dx,sig(mask))
__device__ __align__(16) float g_wt[KKn*Cn*Cn];   // [kk][c][o]
__device__ __align__(16) float g_wt2[Cn*KKn*28];  // om weights: [c][t][28-pad oc]

// ---------------- packed f32x2 helpers (register-only) ----------------
__device__ __forceinline__ ull pk2(float a, float b) {
    ull r; asm("mov.b64 %0, {%1, %2};" : "=l"(r) : "f"(a), "f"(b)); return r;
}
__device__ __forceinline__ void fma2(ull& d, ull a, ull b) {
    asm("fma.rn.f32x2 %0, %1, %2, %0;" : "+l"(d) : "l"(a), "l"(b));
}
__device__ __forceinline__ ull mul2(ull a, ull b) {
    ull r; asm("mul.rn.f32x2 %0, %1, %2;" : "=l"(r) : "l"(a), "l"(b)); return r;
}
__device__ __forceinline__ void upk2(ull v, float& a, float& b) {
    asm("mov.b64 {%0, %1}, %2;" : "=f"(a), "=f"(b) : "l"(v));
}

// ---------------------------------------------------------------------------
// K0b: weight prep.  g_wt[kk][c][o],  g_wt2[c][t][28]
// ---------------------------------------------------------------------------
__global__ void prep_w_k(const float* __restrict__ w_conv,
                         const float* __restrict__ w_om) {
    int i = blockIdx.x * blockDim.x + threadIdx.x;
    if (i < KKn * Cn * Cn) {
        int kk = i / (Cn * Cn);
        int rem = i - kk * Cn * Cn;
        int c = rem >> 6;
        int o = rem & 63;
        g_wt[i] = w_conv[(o * Cn + c) * KKn + kk];
    }
    if (i < Cn * KKn * 28) {
        int c = i / (KKn * 28);
        int r = i - c * (KKn * 28);
        int t = r / 28;
        int oc = r - t * 28;
        g_wt2[i] = (oc < 27) ? w_om[(oc * Cn + c) * KKn + t] : 0.f;
    }
}

// ---------------------------------------------------------------------------
// K1: offset/mask conv (27 out ch, 3x3, pad 1) + bias + sigmoid(mask)
// 16x8 pixel tile, 512 threads: 4-way channel split (16 ch/group),
// smem tree reduction; writes g_offs per (pixel,kk).
// FUSED: also emits the NHWC transpose of x (g_xt) for its interior tile --
// after each staging stage, the 16 staged channels of 128 pixels are written
// out as one float4/thread (channels g*16+s*4..+3 are consecutive).
// grid = 288 -> 2 blocks/SM -> 32 warps/SM.
// ---------------------------------------------------------------------------
__global__ void __launch_bounds__(512, 2) om_conv_k(const float* __restrict__ x,
                                                    const float* __restrict__ b_om) {
    // union: staging (xs 11520 + ws 16128 = 27648 B) vs reduction (2x14848 B)
    __shared__ __align__(16) char osm[29696];
    float* xs   = (float*)osm;              // [16][180]  rows: grp*4 + j
    float* ws   = (float*)(osm + 11520);    // [16][252]
    float* bufA = (float*)osm;              // [128][29]  (reused)
    float* bufB = (float*)(osm + 14848);    // [128][29]

    int b  = blockIdx.z;
    int h0 = blockIdx.y * 8;
    int w0 = blockIdx.x * 16;
    int tid = threadIdx.x;
    int grp = tid >> 7;          // 0..3, channels [grp*16, grp*16+16)
    int lt  = tid & 127;         // pixel id within 16x8 tile
    int tx = lt & 15, ty = lt >> 4;

    // transpose-write roles: thread -> (pixel, channel group)
    int tp = tid >> 2;           // 0..127 pixel
    int tg = tid & 3;            // 0..3 channel group
    int tpx = tp & 15, tpy = tp >> 4;

    ull acc2[14];
#pragma unroll
    for (int i = 0; i < 14; i++) acc2[i] = 0ull;

    const float* xb = x + (size_t)b * Cn * HWn;

    for (int s = 0; s < 4; s++) {
        __syncthreads();
        // stage 16 rows (4 grp x 4 ch) of 18x10 halo tile
        for (int i = tid; i < 2880; i += 512) {
            int row = i / 180;
            int col = i - row * 180;
            int c = (row >> 2) * 16 + s * 4 + (row & 3);
            int gh = h0 - 1 + col / 18, gw = w0 - 1 + col % 18;
            float v = 0.f;
            if (gh >= 0 && gh < Hn && gw >= 0 && gw < Wn)
                v = xb[(size_t)c * HWn + gh * Wn + gw];
            xs[row * 180 + col] = v;
        }
        // stage 16 channels of weights [t][28] each (4032 floats, coalesced)
        for (int i = tid; i < 4032; i += 512) {
            int row = i / 252;
            int off = i - row * 252;
            int c = (row >> 2) * 16 + s * 4 + (row & 3);
            ws[row * 252 + off] = g_wt2[c * 252 + off];
        }
        __syncthreads();

        // FUSED transpose: write this stage's 16 channels of the interior
        // 16x8 tile to g_xt (NHWC). channels tg*16+s*4 .. +3 are consecutive.
        {
            int hoff = (tpy + 1) * 18 + (tpx + 1);
            float4 v;
            v.x = xs[(tg * 4 + 0) * 180 + hoff];
            v.y = xs[(tg * 4 + 1) * 180 + hoff];
            v.z = xs[(tg * 4 + 2) * 180 + hoff];
            v.w = xs[(tg * 4 + 3) * 180 + hoff];
            *(float4*)&g_xt[((size_t)b * HWn + (h0 + tpy) * Wn + w0 + tpx) * Cn
                            + tg * 16 + s * 4] = v;
        }

#pragma unroll
        for (int j = 0; j < 4; j++) {
            const float* xrow = &xs[(grp * 4 + j) * 180];
            const float* wrow = &ws[(grp * 4 + j) * 252];
            float xv[9];
#pragma unroll
            for (int t = 0; t < 9; t++)
                xv[t] = xrow[(ty + t / 3) * 18 + tx + (t % 3)];
#pragma unroll
            for (int t = 0; t < 9; t++) {
                ull xd = pk2(xv[t], xv[t]);
#pragma unroll
                for (int q = 0; q < 7; q++) {
                    float4 w4 = *(const float4*)&wrow[t * 28 + q * 4];
                    ull wlo = pk2(w4.x, w4.y);
                    ull whi = pk2(w4.z, w4.w);
                    fma2(acc2[2 * q], xd, wlo);
                    fma2(acc2[2 * q + 1], xd, whi);
                }
            }
        }
    }

    float acc[28];
#pragma unroll
    for (int j = 0; j < 14; j++) upk2(acc2[j], acc[2 * j], acc[2 * j + 1]);

    // tree reduction over 4 channel groups
    __syncthreads();
    if (grp == 1) {
#pragma unroll
        for (int j = 0; j < 28; j++) bufA[lt * 29 + j] = acc[j];
    }
    if (grp == 3) {
#pragma unroll
        for (int j = 0; j < 28; j++) bufB[lt * 29 + j] = acc[j];
    }
    __syncthreads();
    if (grp == 0) {
#pragma unroll
        for (int j = 0; j < 28; j++) acc[j] += bufA[lt * 29 + j];
    }
    if (grp == 2) {
#pragma unroll
        for (int j = 0; j < 28; j++) acc[j] += bufB[lt * 29 + j];
    }
    __syncthreads();
    if (grp == 2) {
#pragma unroll
        for (int j = 0; j < 28; j++) bufA[lt * 29 + j] = acc[j];
    }
    __syncthreads();
    if (grp == 0) {
#pragma unroll
        for (int j = 0; j < 28; j++) acc[j] += bufA[lt * 29 + j];

        int h = h0 + ty, w = w0 + tx;
        float* op = g_offs + ((size_t)b * HWn + h * Wn + w) * 27;
#pragma unroll
        for (int kk = 0; kk < 9; kk++) {
            float dy = acc[2 * kk]     + b_om[2 * kk];
            float dx = acc[2 * kk + 1] + b_om[2 * kk + 1];
            float mv = acc[18 + kk]    + b_om[18 + kk];
            mv = 1.f / (1.f + expf(-mv));
            op[3 * kk]     = dy;
            op[3 * kk + 1] = dx;
            op[3 * kk + 2] = mv;
        }
    }
}

// ---------------------------------------------------------------------------
// K2: fused bilinear sampling + (pix x o) GEMM + BN + SiLU  (R12, unchanged)
// warp spans 8 p_grps x 4 o_grps (sv: 1 phase, wv: 1 phase per K-step)
// ---------------------------------------------------------------------------
__global__ void __launch_bounds__(256) main_k(const float* __restrict__ gamma,
                                              const float* __restrict__ beta,
                                              const float* __restrict__ rmean,
                                              const float* __restrict__ rvar,
                                              float* __restrict__ out) {
    __shared__ __align__(16) int4   s_off4[64];   // 4 corner offsets per pixel
    __shared__ __align__(16) float4 s_bw4[64];    // 4 folded bilinear weights
    __shared__ __align__(16) float  sA[64 * 68];  // sampled [c][rot-col]
    __shared__ __align__(16) float  sW[64 * 64];  // w tile [c][o]

    int b  = blockIdx.z;
    int h0 = blockIdx.y * 4;
    int w0 = blockIdx.x * 16;
    int tid = threadIdx.x;

    // warp spans 8 p_grps x 4 o_grps
    int o_grp = ((tid >> 6) << 2) + (tid & 3);               // 0..15
    int p_grp = (((tid >> 5) & 1) << 3) + ((tid >> 2) & 7);  // 0..15

    // staging roles: 16 threads cover 64 channels of one pixel
    int kq = tid & 15;         // channel quad: c0 = kq*4
    int ps = tid >> 4;         // pixel-slot within each pass of 16 pixels
    int c0s = kq * 4;

    ull acc2[8];
#pragma unroll
    for (int i = 0; i < 8; i++) acc2[i] = 0ull;

    const float* xb = g_xt + (size_t)b * HWn * Cn;

    for (int kk = 0; kk < 9; kk++) {
        // --- per-kk coords: 64 threads, one per pixel ---
        if (tid < 64) {
            int prow = tid >> 4, pcol = tid & 15;
            int ho = h0 + prow, wo = w0 + pcol;
            const float* op = g_offs + ((size_t)b * HWn + ho * Wn + wo) * 27 + 3 * kk;
            float dy = op[0], dx = op[1], m = op[2];
            float py = (float)(ho - 1 + kk / 3) + dy;
            float px = (float)(wo - 1 + kk % 3) + dx;
            float y0f = floorf(py), x0f = floorf(px);
            float ly = py - y0f, lx = px - x0f;
            int y0 = (int)y0f, x0 = (int)x0f;
            int y1 = y0 + 1, x1 = x0 + 1;
            float vy0 = (y0 >= 0 && y0 < Hn) ? 1.f : 0.f;
            float vy1 = (y1 >= 0 && y1 < Hn) ? 1.f : 0.f;
            float vx0 = (x0 >= 0 && x0 < Wn) ? 1.f : 0.f;
            float vx1 = (x1 >= 0 && x1 < Wn) ? 1.f : 0.f;
            float4 bw;
            bw.x = (1.f - ly) * (1.f - lx) * m * vy0 * vx0;
            bw.y = (1.f - ly) * lx         * m * vy0 * vx1;
            bw.z = ly * (1.f - lx)         * m * vy1 * vx0;
            bw.w = ly * lx                 * m * vy1 * vx1;
            int y0c = min(max(y0, 0), Hn - 1), y1c = min(max(y1, 0), Hn - 1);
            int x0c = min(max(x0, 0), Wn - 1), x1c = min(max(x1, 0), Wn - 1);
            int4 q;
            q.x = (y0c * Wn + x0c) * Cn;
            q.y = (y0c * Wn + x1c) * Cn;
            q.z = (y1c * Wn + x0c) * Cn;
            q.w = (y1c * Wn + x1c) * Cn;
            s_off4[tid] = q;
            s_bw4[tid]  = bw;
        }
        __syncthreads();

        // --- stage sA: 4 passes; per pass, 16 lanes span one pixel's 256B row ---
#pragma unroll
        for (int it = 0; it < 4; it++) {
            int pix = it * 16 + ps;
            int4   q  = s_off4[pix];
            float4 bw = s_bw4[pix];
            float4 v00 = *(const float4*)(xb + q.x + c0s);
            float4 v01 = *(const float4*)(xb + q.y + c0s);
            float4 v10 = *(const float4*)(xb + q.z + c0s);
            float4 v11 = *(const float4*)(xb + q.w + c0s);
            ull pw00 = pk2(bw.x, bw.x), pw01 = pk2(bw.y, bw.y);
            ull pw10 = pk2(bw.z, bw.z), pw11 = pk2(bw.w, bw.w);
            ull r0 = mul2(pw00, pk2(v00.x, v00.y));
            fma2(r0, pw01, pk2(v01.x, v01.y));
            fma2(r0, pw10, pk2(v10.x, v10.y));
            fma2(r0, pw11, pk2(v11.x, v11.y));
            ull r1 = mul2(pw00, pk2(v00.z, v00.w));
            fma2(r1, pw01, pk2(v01.z, v01.w));
            fma2(r1, pw10, pk2(v10.z, v10.w));
            fma2(r1, pw11, pk2(v11.z, v11.w));
            float f0, f1, f2, f3;
            upk2(r0, f0, f1); upk2(r1, f2, f3);
            int colp = (pix + c0s) & 63;          // rotated column
            sA[(c0s + 0) * 68 + colp] = f0;
            sA[(c0s + 1) * 68 + colp] = f1;
            sA[(c0s + 2) * 68 + colp] = f2;
            sA[(c0s + 3) * 68 + colp] = f3;
        }
        // W tile: 4096 floats, coalesced float4
        {
            const float4* src = (const float4*)(g_wt + kk * Cn * Cn);
            float4* dst = (float4*)sW;
#pragma unroll
            for (int i = 0; i < 4; i++) dst[tid + i * 256] = src[tid + i * 256];
        }
        __syncthreads();

        // --- GEMM: 64 K-steps, 4p x 4o micro-tile, packed f32x2 ---
#pragma unroll 16
        for (int cl = 0; cl < 64; cl++) {
            int col = (p_grp * 4 + (cl & 60)) & 63;   // undo rotation
            float4 sv = *(const float4*)&sA[cl * 68 + col];
            float4 wv = *(const float4*)&sW[cl * 64 + o_grp * 4];
            ull wlo = pk2(wv.x, wv.y), whi = pk2(wv.z, wv.w);
            ull sp0 = pk2(sv.x, sv.x), sp1 = pk2(sv.y, sv.y);
            ull sp2 = pk2(sv.z, sv.z), sp3 = pk2(sv.w, sv.w);
            fma2(acc2[0], sp0, wlo); fma2(acc2[1], sp0, whi);
            fma2(acc2[2], sp1, wlo); fma2(acc2[3], sp1, whi);
            fma2(acc2[4], sp2, wlo); fma2(acc2[5], sp2, whi);
            fma2(acc2[6], sp3, wlo); fma2(acc2[7], sp3, whi);
        }
        __syncthreads();
    }

    // --- epilogue: BN + SiLU, write NCHW ---
    float acc[16];
#pragma unroll
    for (int p = 0; p < 4; p++) {
        upk2(acc2[p * 2 + 0], acc[p * 4 + 0], acc[p * 4 + 1]);
        upk2(acc2[p * 2 + 1], acc[p * 4 + 2], acc[p * 4 + 3]);
    }

    int o0 = o_grp * 4;
    int prow = p_grp >> 2;
    int col0 = (p_grp & 3) * 4;
    int ho = h0 + prow, wo = w0 + col0;
#pragma unroll
    for (int j = 0; j < 4; j++) {
        int o = o0 + j;
        float sc = gamma[o] * rsqrtf(rvar[o] + 1e-5f);
        float sh = beta[o] - rmean[o] * sc;
        float4 r;
        float v;
        v = acc[0 * 4 + j] * sc + sh; r.x = v / (1.f + expf(-v));
        v = acc[1 * 4 + j] * sc + sh; r.y = v / (1.f + expf(-v));
        v = acc[2 * 4 + j] * sc + sh; r.z = v / (1.f + expf(-v));
        v = acc[3 * 4 + j] * sc + sh; r.w = v / (1.f + expf(-v));
        *(float4*)&out[(((size_t)b * Cn + o) * Hn + ho) * Wn + wo] = r;
    }
}

// ---------------------------------------------------------------------------
extern "C" void kernel_launch(void* const* d_in, const int* in_sizes, int n_in,
                              void* d_out, int out_size) {
    const float* x      = (const float*)d_in[0];
    const float* w_om   = (const float*)d_in[1];
    const float* b_om   = (const float*)d_in[2];
    const float* w_conv = (const float*)d_in[3];
    const float* gamma  = (const float*)d_in[4];
    const float* beta   = (const float*)d_in[5];
    const float* rmean  = (const float*)d_in[6];
    const float* rvar   = (const float*)d_in[7];
    float* out = (float*)d_out;

    prep_w_k<<<(KKn * Cn * Cn + 1023) / 1024, 1024>>>(w_conv, w_om);
    om_conv_k<<<dim3(Wn / 16, Hn / 8, Bn), 512>>>(x, b_om);
    main_k<<<dim3(Wn / 16, Hn / 4, Bn), 256>>>(gamma, beta, rmean, rvar, out);
}

// round 16
// speedup vs baseline: 1.0113x; 1.0113x over previous
#include <cuda_runtime.h>
#include <cuda_bf16.h>
#include <cstdint>
#include <math.h>

#define Bn 4
#define Cn 64
#define Hn 96
#define Wn 96
#define HWn (Hn*Wn)
#define KKn 9

typedef unsigned long long ull;

// Scratch (device globals -- no dynamic allocation allowed)
__device__ __align__(16) float g_xt[Bn*HWn*Cn];   // x in NHWC: [b][h][w][c]
__device__ __align__(16) float g_offs[Bn*HWn*27]; // per pixel: 9 x (dy,dx,sig(mask))
__device__ __align__(16) float g_wt[KKn*Cn*Cn];   // [kk][c][o]
__device__ __align__(16) float g_wt2[Cn*KKn*28];  // om weights: [c][t][28-pad oc]

// ---------------- packed f32x2 helpers (register-only) ----------------
__device__ __forceinline__ ull pk2(float a, float b) {
    ull r; asm("mov.b64 %0, {%1, %2};" : "=l"(r) : "f"(a), "f"(b)); return r;
}
__device__ __forceinline__ void fma2(ull& d, ull a, ull b) {
    asm("fma.rn.f32x2 %0, %1, %2, %0;" : "+l"(d) : "l"(a), "l"(b));
}
__device__ __forceinline__ ull mul2(ull a, ull b) {
    ull r; asm("mul.rn.f32x2 %0, %1, %2;" : "=l"(r) : "l"(a), "l"(b)); return r;
}
__device__ __forceinline__ void upk2(ull v, float& a, float& b) {
    asm("mov.b64 {%0, %1}, %2;" : "=f"(a), "=f"(b) : "l"(v));
}

// ---------------------------------------------------------------------------
// K0b: weight prep.  g_wt[kk][c][o],  g_wt2[c][t][28]
// ---------------------------------------------------------------------------
__global__ void prep_w_k(const float* __restrict__ w_conv,
                         const float* __restrict__ w_om) {
    int i = blockIdx.x * blockDim.x + threadIdx.x;
    if (i < KKn * Cn * Cn) {
        int kk = i / (Cn * Cn);
        int rem = i - kk * Cn * Cn;
        int c = rem >> 6;
        int o = rem & 63;
        g_wt[i] = w_conv[(o * Cn + c) * KKn + kk];
    }
    if (i < Cn * KKn * 28) {
        int c = i / (KKn * 28);
        int r = i - c * (KKn * 28);
        int t = r / 28;
        int oc = r - t * 28;
        g_wt2[i] = (oc < 27) ? w_om[(oc * Cn + c) * KKn + t] : 0.f;
    }
}

// ---------------------------------------------------------------------------
// K1: offset/mask conv (27 out ch, 3x3, pad 1) + bias + sigmoid(mask)
// 16x8 pixel tile, 512 threads: 4-way channel split (16 ch/group),
// smem tree reduction; writes g_offs per (pixel,kk).
// FUSED: also emits the NHWC transpose of x (g_xt) for its interior tile.
// ---------------------------------------------------------------------------
__global__ void __launch_bounds__(512, 2) om_conv_k(const float* __restrict__ x,
                                                    const float* __restrict__ b_om) {
    // union: staging (xs 11520 + ws 16128 = 27648 B) vs reduction (2x14848 B)
    __shared__ __align__(16) char osm[29696];
    float* xs   = (float*)osm;              // [16][180]  rows: grp*4 + j
    float* ws   = (float*)(osm + 11520);    // [16][252]
    float* bufA = (float*)osm;              // [128][29]  (reused)
    float* bufB = (float*)(osm + 14848);    // [128][29]

    int b  = blockIdx.z;
    int h0 = blockIdx.y * 8;
    int w0 = blockIdx.x * 16;
    int tid = threadIdx.x;
    int grp = tid >> 7;          // 0..3, channels [grp*16, grp*16+16)
    int lt  = tid & 127;         // pixel id within 16x8 tile
    int tx = lt & 15, ty = lt >> 4;

    // transpose-write roles: thread -> (pixel, channel group)
    int tp = tid >> 2;           // 0..127 pixel
    int tg = tid & 3;            // 0..3 channel group
    int tpx = tp & 15, tpy = tp >> 4;

    ull acc2[14];
#pragma unroll
    for (int i = 0; i < 14; i++) acc2[i] = 0ull;

    const float* xb = x + (size_t)b * Cn * HWn;

    for (int s = 0; s < 4; s++) {
        __syncthreads();
        // stage 16 rows (4 grp x 4 ch) of 18x10 halo tile
        for (int i = tid; i < 2880; i += 512) {
            int row = i / 180;
            int col = i - row * 180;
            int c = (row >> 2) * 16 + s * 4 + (row & 3);
            int gh = h0 - 1 + col / 18, gw = w0 - 1 + col % 18;
            float v = 0.f;
            if (gh >= 0 && gh < Hn && gw >= 0 && gw < Wn)
                v = xb[(size_t)c * HWn + gh * Wn + gw];
            xs[row * 180 + col] = v;
        }
        // stage 16 channels of weights [t][28] each (4032 floats, coalesced)
        for (int i = tid; i < 4032; i += 512) {
            int row = i / 252;
            int off = i - row * 252;
            int c = (row >> 2) * 16 + s * 4 + (row & 3);
            ws[row * 252 + off] = g_wt2[c * 252 + off];
        }
        __syncthreads();

        // FUSED transpose: write this stage's 16 channels of the interior
        // 16x8 tile to g_xt (NHWC). channels tg*16+s*4 .. +3 are consecutive.
        {
            int hoff = (tpy + 1) * 18 + (tpx + 1);
            float4 v;
            v.x = xs[(tg * 4 + 0) * 180 + hoff];
            v.y = xs[(tg * 4 + 1) * 180 + hoff];
            v.z = xs[(tg * 4 + 2) * 180 + hoff];
            v.w = xs[(tg * 4 + 3) * 180 + hoff];
            *(float4*)&g_xt[((size_t)b * HWn + (h0 + tpy) * Wn + w0 + tpx) * Cn
                            + tg * 16 + s * 4] = v;
        }

#pragma unroll
        for (int j = 0; j < 4; j++) {
            const float* xrow = &xs[(grp * 4 + j) * 180];
            const float* wrow = &ws[(grp * 4 + j) * 252];
            float xv[9];
#pragma unroll
            for (int t = 0; t < 9; t++)
                xv[t] = xrow[(ty + t / 3) * 18 + tx + (t % 3)];
#pragma unroll
            for (int t = 0; t < 9; t++) {
                ull xd = pk2(xv[t], xv[t]);
#pragma unroll
                for (int q = 0; q < 7; q++) {
                    float4 w4 = *(const float4*)&wrow[t * 28 + q * 4];
                    ull wlo = pk2(w4.x, w4.y);
                    ull whi = pk2(w4.z, w4.w);
                    fma2(acc2[2 * q], xd, wlo);
                    fma2(acc2[2 * q + 1], xd, whi);
                }
            }
        }
    }

    float acc[28];
#pragma unroll
    for (int j = 0; j < 14; j++) upk2(acc2[j], acc[2 * j], acc[2 * j + 1]);

    // tree reduction over 4 channel groups
    __syncthreads();
    if (grp == 1) {
#pragma unroll
        for (int j = 0; j < 28; j++) bufA[lt * 29 + j] = acc[j];
    }
    if (grp == 3) {
#pragma unroll
        for (int j = 0; j < 28; j++) bufB[lt * 29 + j] = acc[j];
    }
    __syncthreads();
    if (grp == 0) {
#pragma unroll
        for (int j = 0; j < 28; j++) acc[j] += bufA[lt * 29 + j];
    }
    if (grp == 2) {
#pragma unroll
        for (int j = 0; j < 28; j++) acc[j] += bufB[lt * 29 + j];
    }
    __syncthreads();
    if (grp == 2) {
#pragma unroll
        for (int j = 0; j < 28; j++) bufA[lt * 29 + j] = acc[j];
    }
    __syncthreads();
    if (grp == 0) {
#pragma unroll
        for (int j = 0; j < 28; j++) acc[j] += bufA[lt * 29 + j];

        int h = h0 + ty, w = w0 + tx;
        float* op = g_offs + ((size_t)b * HWn + h * Wn + w) * 27;
#pragma unroll
        for (int kk = 0; kk < 9; kk++) {
            float dy = acc[2 * kk]     + b_om[2 * kk];
            float dx = acc[2 * kk + 1] + b_om[2 * kk + 1];
            float mv = acc[18 + kk]    + b_om[18 + kk];
            mv = 1.f / (1.f + expf(-mv));
            op[3 * kk]     = dy;
            op[3 * kk + 1] = dx;
            op[3 * kk + 2] = mv;
        }
    }
}

// ---------------------------------------------------------------------------
// K2: fused bilinear sampling + (pix x o) GEMM + BN + SiLU
// R12 GEMM mapping; W tile read DIRECTLY from g_wt via __ldg (L1-resident,
// shared by all blocks) -- no sW smem, no W staging.
// ---------------------------------------------------------------------------
__global__ void __launch_bounds__(256) main_k(const float* __restrict__ gamma,
                                              const float* __restrict__ beta,
                                              const float* __restrict__ rmean,
                                              const float* __restrict__ rvar,
                                              float* __restrict__ out) {
    __shared__ __align__(16) int4   s_off4[64];   // 4 corner offsets per pixel
    __shared__ __align__(16) float4 s_bw4[64];    // 4 folded bilinear weights
    __shared__ __align__(16) float  sA[64 * 68];  // sampled [c][rot-col]

    int b  = blockIdx.z;
    int h0 = blockIdx.y * 4;
    int w0 = blockIdx.x * 16;
    int tid = threadIdx.x;

    // warp spans 8 p_grps x 4 o_grps
    int o_grp = ((tid >> 6) << 2) + (tid & 3);               // 0..15
    int p_grp = (((tid >> 5) & 1) << 3) + ((tid >> 2) & 7);  // 0..15

    // staging roles: 16 threads cover 64 channels of one pixel
    int kq = tid & 15;         // channel quad: c0 = kq*4
    int ps = tid >> 4;         // pixel-slot within each pass of 16 pixels
    int c0s = kq * 4;

    ull acc2[8];
#pragma unroll
    for (int i = 0; i < 8; i++) acc2[i] = 0ull;

    const float* xb = g_xt + (size_t)b * HWn * Cn;
    const float4* wbase = (const float4*)g_wt + o_grp;  // + cl*16 per row

    for (int kk = 0; kk < 9; kk++) {
        // --- per-kk coords: 64 threads, one per pixel ---
        if (tid < 64) {
            int prow = tid >> 4, pcol = tid & 15;
            int ho = h0 + prow, wo = w0 + pcol;
            const float* op = g_offs + ((size_t)b * HWn + ho * Wn + wo) * 27 + 3 * kk;
            float dy = op[0], dx = op[1], m = op[2];
            float py = (float)(ho - 1 + kk / 3) + dy;
            float px = (float)(wo - 1 + kk % 3) + dx;
            float y0f = floorf(py), x0f = floorf(px);
            float ly = py - y0f, lx = px - x0f;
            int y0 = (int)y0f, x0 = (int)x0f;
            int y1 = y0 + 1, x1 = x0 + 1;
            float vy0 = (y0 >= 0 && y0 < Hn) ? 1.f : 0.f;
            float vy1 = (y1 >= 0 && y1 < Hn) ? 1.f : 0.f;
            float vx0 = (x0 >= 0 && x0 < Wn) ? 1.f : 0.f;
            float vx1 = (x1 >= 0 && x1 < Wn) ? 1.f : 0.f;
            float4 bw;
            bw.x = (1.f - ly) * (1.f - lx) * m * vy0 * vx0;
            bw.y = (1.f - ly) * lx         * m * vy0 * vx1;
            bw.z = ly * (1.f - lx)         * m * vy1 * vx0;
            bw.w = ly * lx                 * m * vy1 * vx1;
            int y0c = min(max(y0, 0), Hn - 1), y1c = min(max(y1, 0), Hn - 1);
            int x0c = min(max(x0, 0), Wn - 1), x1c = min(max(x1, 0), Wn - 1);
            int4 q;
            q.x = (y0c * Wn + x0c) * Cn;
            q.y = (y0c * Wn + x1c) * Cn;
            q.z = (y1c * Wn + x0c) * Cn;
            q.w = (y1c * Wn + x1c) * Cn;
            s_off4[tid] = q;
            s_bw4[tid]  = bw;
        }
        __syncthreads();

        // --- stage sA: 4 passes; per pass, 16 lanes span one pixel's 256B row ---
#pragma unroll
        for (int it = 0; it < 4; it++) {
            int pix = it * 16 + ps;
            int4   q  = s_off4[pix];
            float4 bw = s_bw4[pix];
            float4 v00 = *(const float4*)(xb + q.x + c0s);
            float4 v01 = *(const float4*)(xb + q.y + c0s);
            float4 v10 = *(const float4*)(xb + q.z + c0s);
            float4 v11 = *(const float4*)(xb + q.w + c0s);
            ull pw00 = pk2(bw.x, bw.x), pw01 = pk2(bw.y, bw.y);
            ull pw10 = pk2(bw.z, bw.z), pw11 = pk2(bw.w, bw.w);
            ull r0 = mul2(pw00, pk2(v00.x, v00.y));
            fma2(r0, pw01, pk2(v01.x, v01.y));
            fma2(r0, pw10, pk2(v10.x, v10.y));
            fma2(r0, pw11, pk2(v11.x, v11.y));
            ull r1 = mul2(pw00, pk2(v00.z, v00.w));
            fma2(r1, pw01, pk2(v01.z, v01.w));
            fma2(r1, pw10, pk2(v10.z, v10.w));
            fma2(r1, pw11, pk2(v11.z, v11.w));
            float f0, f1, f2, f3;
            upk2(r0, f0, f1); upk2(r1, f2, f3);
            int colp = (pix + c0s) & 63;          // rotated column
            sA[(c0s + 0) * 68 + colp] = f0;
            sA[(c0s + 1) * 68 + colp] = f1;
            sA[(c0s + 2) * 68 + colp] = f2;
            sA[(c0s + 3) * 68 + colp] = f3;
        }
        __syncthreads();

        // --- GEMM: 64 K-steps, 4p x 4o micro-tile, packed f32x2 ---
        const float4* wkk = wbase + kk * 1024;    // [cl][16 float4 groups]
#pragma unroll 16
        for (int cl = 0; cl < 64; cl++) {
            int col = (p_grp * 4 + (cl & 60)) & 63;   // undo rotation
            float4 sv = *(const float4*)&sA[cl * 68 + col];
            float4 wv = __ldg(wkk + cl * 16);
            ull wlo = pk2(wv.x, wv.y), whi = pk2(wv.z, wv.w);
            ull sp0 = pk2(sv.x, sv.x), sp1 = pk2(sv.y, sv.y);
            ull sp2 = pk2(sv.z, sv.z), sp3 = pk2(sv.w, sv.w);
            fma2(acc2[0], sp0, wlo); fma2(acc2[1], sp0, whi);
            fma2(acc2[2], sp1, wlo); fma2(acc2[3], sp1, whi);
            fma2(acc2[4], sp2, wlo); fma2(acc2[5], sp2, whi);
            fma2(acc2[6], sp3, wlo); fma2(acc2[7], sp3, whi);
        }
        __syncthreads();
    }

    // --- epilogue: BN + SiLU, write NCHW ---
    float acc[16];
#pragma unroll
    for (int p = 0; p < 4; p++) {
        upk2(acc2[p * 2 + 0], acc[p * 4 + 0], acc[p * 4 + 1]);
        upk2(acc2[p * 2 + 1], acc[p * 4 + 2], acc[p * 4 + 3]);
    }

    int o0 = o_grp * 4;
    int prow = p_grp >> 2;
    int col0 = (p_grp & 3) * 4;
    int ho = h0 + prow, wo = w0 + col0;
#pragma unroll
    for (int j = 0; j < 4; j++) {
        int o = o0 + j;
        float sc = gamma[o] * rsqrtf(rvar[o] + 1e-5f);
        float sh = beta[o] - rmean[o] * sc;
        float4 r;
        float v;
        v = acc[0 * 4 + j] * sc + sh; r.x = v / (1.f + expf(-v));
        v = acc[1 * 4 + j] * sc + sh; r.y = v / (1.f + expf(-v));
        v = acc[2 * 4 + j] * sc + sh; r.z = v / (1.f + expf(-v));
        v = acc[3 * 4 + j] * sc + sh; r.w = v / (1.f + expf(-v));
        *(float4*)&out[(((size_t)b * Cn + o) * Hn + ho) * Wn + wo] = r;
    }
}

// ---------------------------------------------------------------------------
extern "C" void kernel_launch(void* const* d_in, const int* in_sizes, int n_in,
                              void* d_out, int out_size) {
    const float* x      = (const float*)d_in[0];
    const float* w_om   = (const float*)d_in[1];
    const float* b_om   = (const float*)d_in[2];
    const float* w_conv = (const float*)d_in[3];
    const float* gamma  = (const float*)d_in[4];
    const float* beta   = (const float*)d_in[5];
    const float* rmean  = (const float*)d_in[6];
    const float* rvar   = (const float*)d_in[7];
    float* out = (float*)d_out;

    prep_w_k<<<(KKn * Cn * Cn + 1023) / 1024, 1024>>>(w_conv, w_om);
    om_conv_k<<<dim3(Wn / 16, Hn / 8, Bn), 512>>>(x, b_om);
    main_k<<<dim3(Wn / 16, Hn / 4, Bn), 256>>>(gamma, beta, rmean, rvar, out);
}